// round 5
// baseline (speedup 1.0000x reference)
#include <cuda_runtime.h>
#include <stdint.h>

typedef unsigned long long ull;

// ---------------------------------------------------------------------------
// Blackwell packed-fp32 helpers (FFMA2: 2x fp32 FMA per instruction)
// ---------------------------------------------------------------------------
__device__ __forceinline__ ull ffma2(ull a, ull b, ull c) {
    ull d;
    asm("fma.rn.f32x2 %0, %1, %2, %3;" : "=l"(d) : "l"(a), "l"(b), "l"(c));
    return d;
}
__device__ __forceinline__ ull dup2(float x) {
    ull d;
    asm("mov.b64 %0, {%1, %1};" : "=l"(d) : "f"(x));
    return d;
}
__device__ __forceinline__ float2 unpk(ull v) {
    float2 f;
    asm("mov.b64 {%0, %1}, %2;" : "=f"(f.x), "=f"(f.y) : "l"(v));
    return f;
}
__device__ __forceinline__ float silu_f(float g) {
    return g / (1.f + __expf(-g));
}

#define M_TOT 4096
#define K1    4096
#define N1    11008
#define N2    4096

// intermediate h = silu(gate) * up, fp32, 4096 x 11008 (~180 MB scratch)
__device__ float g_hbuf[(size_t)M_TOT * (size_t)N1];

// ---------------------------------------------------------------------------
// Kernel A: gate+up GEMM (M=4096, K=4096, N=11008) + silu*mul -> g_hbuf
// Block tile: 128(M) x 64(N) x 8(K). 256 threads. Thread tile: 8(M)x4(N) for
// BOTH gate and up. Accumulators packed 2-wide along M (f32x2).
// ---------------------------------------------------------------------------
__global__ __launch_bounds__(256)
void gateup_kernel(const float* __restrict__ x,
                   const int*   __restrict__ gqw, const float* __restrict__ gsc, const int* __restrict__ gqz,
                   const int*   __restrict__ uqw, const float* __restrict__ usc, const int* __restrict__ uqz)
{
    __shared__ float As[2][8][132];   // As[k][m], padded stride (conflict-free)
    __shared__ float Bg[2][8][68];    // dequantized gate tile [k][n]
    __shared__ float Bu[2][8][68];    // dequantized up tile   [k][n]

    const int tid = threadIdx.x;
    const int tx  = tid & 15;         // n-quad  (0..15) -> n = tx*4
    const int ty  = tid >> 4;         // m-octet (0..15) -> m = ty*8
    const int n0  = blockIdx.x * 64;
    const int m0  = blockIdx.y * 128;

    // A-tile loader: 256 threads * float4 = 128 rows x 8 k
    const int am = tid >> 1, aq = tid & 1;
    const float* xp = x + (size_t)(m0 + am) * K1 + aq * 4;

    // B-tile loader: 128 threads per matrix, 64 cols x 2 k-halves
    const int bn   = tid & 63;
    const int bh   = (tid >> 6) & 1;
    const int bmat = tid >> 7;
    const int gn   = n0 + bn;
    const int*   qw = bmat ? uqw : gqw;
    const float* sc = bmat ? usc : gsc;
    const int*   qz = bmat ? uqz : gqz;
    float* Bbase = bmat ? &Bu[0][0][0] : &Bg[0][0][0];

    ull cg[4][4], cu[4][4];
#pragma unroll
    for (int i = 0; i < 4; i++)
#pragma unroll
        for (int j = 0; j < 4; j++) { cg[i][j] = 0ull; cu[i][j] = 0ull; }

    float4 av; uint32_t qv, zv; float sv;

#define LOADREGS_A(k0) do {                                                      \
    av = *(const float4*)(xp + (k0));                                            \
    qv = (uint32_t)__ldg(qw + (size_t)((k0) >> 3) * N1 + gn);                    \
    sv = __ldg(sc + (size_t)((k0) >> 7) * N1 + gn);                              \
    zv = (uint32_t)__ldg(qz + (size_t)((k0) >> 7) * (N1 / 8) + (gn >> 3));       \
} while (0)

#define STORESMEM_A(st) do {                                                     \
    As[st][aq*4+0][am] = av.x; As[st][aq*4+1][am] = av.y;                        \
    As[st][aq*4+2][am] = av.z; As[st][aq*4+3][am] = av.w;                        \
    float zt = ((float)((zv >> ((gn & 7) * 4)) & 15) + 1.f) * sv;                \
    uint32_t qs = qv >> (bh * 16);                                               \
    float* Bp = Bbase + (st) * (8 * 68) + (bh * 4) * 68 + bn;                    \
    Bp[0*68] = (float)( qs        & 15) * sv - zt;                               \
    Bp[1*68] = (float)((qs >>  4) & 15) * sv - zt;                               \
    Bp[2*68] = (float)((qs >>  8) & 15) * sv - zt;                               \
    Bp[3*68] = (float)((qs >> 12) & 15) * sv - zt;                               \
} while (0)

    LOADREGS_A(0);
    STORESMEM_A(0);
    __syncthreads();

    const int STEPS = K1 / 8;   // 512
    for (int step = 0; step < STEPS; ++step) {
        const int cur = step & 1;
        if (step + 1 < STEPS) LOADREGS_A((step + 1) * 8);

#pragma unroll
        for (int kk = 0; kk < 8; kk++) {
            ull a[4];
#pragma unroll
            for (int i = 0; i < 4; i++)
                a[i] = *(const ull*)&As[cur][kk][ty * 8 + 2 * i];
            float4 bg4 = *(const float4*)&Bg[cur][kk][tx * 4];
            float4 bu4 = *(const float4*)&Bu[cur][kk][tx * 4];
            ull bgd[4] = {dup2(bg4.x), dup2(bg4.y), dup2(bg4.z), dup2(bg4.w)};
            ull bud[4] = {dup2(bu4.x), dup2(bu4.y), dup2(bu4.z), dup2(bu4.w)};
#pragma unroll
            for (int i = 0; i < 4; i++)
#pragma unroll
                for (int j = 0; j < 4; j++) {
                    cg[i][j] = ffma2(a[i], bgd[j], cg[i][j]);
                    cu[i][j] = ffma2(a[i], bud[j], cu[i][j]);
                }
        }
        if (step + 1 < STEPS) STORESMEM_A((step + 1) & 1);
        __syncthreads();
    }
#undef LOADREGS_A
#undef STORESMEM_A

    // epilogue: h = silu(g) * u
#pragma unroll
    for (int i = 0; i < 4; i++) {
        float r0[4], r1[4];
#pragma unroll
        for (int j = 0; j < 4; j++) {
            float2 g2 = unpk(cg[i][j]);
            float2 u2 = unpk(cu[i][j]);
            r0[j] = silu_f(g2.x) * u2.x;
            r1[j] = silu_f(g2.y) * u2.y;
        }
        const int m = m0 + ty * 8 + i * 2;
        float* hp = g_hbuf + (size_t)m * N1 + n0 + tx * 4;
        *(float4*)hp         = make_float4(r0[0], r0[1], r0[2], r0[3]);
        *(float4*)(hp + N1)  = make_float4(r1[0], r1[1], r1[2], r1[3]);
    }
}

// ---------------------------------------------------------------------------
// Kernel B: down GEMM out = h @ Wd  (M=4096, K=11008, N=4096)
// Block tile: 128(M) x 128(N) x 8(K). 256 threads. Thread tile: 8(M)x8(N).
// ---------------------------------------------------------------------------
__global__ __launch_bounds__(256)
void down_kernel(const int* __restrict__ dqw, const float* __restrict__ dsc,
                 const int* __restrict__ dqz, float* __restrict__ out)
{
    __shared__ float As[2][8][132];
    __shared__ float Bs[2][8][132];

    const int tid = threadIdx.x;
    const int tx  = tid & 15;         // n = tx*8
    const int ty  = tid >> 4;         // m = ty*8
    const int n0  = blockIdx.x * 128;
    const int m0  = blockIdx.y * 128;

    const int am = tid >> 1, aq = tid & 1;
    const float* hp = g_hbuf + (size_t)(m0 + am) * N1 + aq * 4;

    const int bn = tid & 127;
    const int bh = tid >> 7;
    const int gn = n0 + bn;

    ull c[4][8];
#pragma unroll
    for (int i = 0; i < 4; i++)
#pragma unroll
        for (int j = 0; j < 8; j++) c[i][j] = 0ull;

    float4 av; uint32_t qv, zv; float sv;

#define LOADREGS_B(k0) do {                                                      \
    av = *(const float4*)(hp + (k0));                                            \
    qv = (uint32_t)__ldg(dqw + (size_t)((k0) >> 3) * N2 + gn);                   \
    sv = __ldg(dsc + (size_t)((k0) >> 7) * N2 + gn);                             \
    zv = (uint32_t)__ldg(dqz + (size_t)((k0) >> 7) * (N2 / 8) + (gn >> 3));      \
} while (0)

#define STORESMEM_B(st) do {                                                     \
    As[st][aq*4+0][am] = av.x; As[st][aq*4+1][am] = av.y;                        \
    As[st][aq*4+2][am] = av.z; As[st][aq*4+3][am] = av.w;                        \
    float zt = ((float)((zv >> ((gn & 7) * 4)) & 15) + 1.f) * sv;                \
    uint32_t qs = qv >> (bh * 16);                                               \
    Bs[st][bh*4+0][bn] = (float)( qs        & 15) * sv - zt;                     \
    Bs[st][bh*4+1][bn] = (float)((qs >>  4) & 15) * sv - zt;                     \
    Bs[st][bh*4+2][bn] = (float)((qs >>  8) & 15) * sv - zt;                     \
    Bs[st][bh*4+3][bn] = (float)((qs >> 12) & 15) * sv - zt;                     \
} while (0)

    LOADREGS_B(0);
    STORESMEM_B(0);
    __syncthreads();

    const int STEPS = N1 / 8;   // 1376 (K dim of this GEMM is 11008)
    for (int step = 0; step < STEPS; ++step) {
        const int cur = step & 1;
        if (step + 1 < STEPS) LOADREGS_B((step + 1) * 8);

#pragma unroll
        for (int kk = 0; kk < 8; kk++) {
            ull a[4];
#pragma unroll
            for (int i = 0; i < 4; i++)
                a[i] = *(const ull*)&As[cur][kk][ty * 8 + 2 * i];
            float4 b0 = *(const float4*)&Bs[cur][kk][tx * 8];
            float4 b1 = *(const float4*)&Bs[cur][kk][tx * 8 + 4];
            ull bd[8] = {dup2(b0.x), dup2(b0.y), dup2(b0.z), dup2(b0.w),
                         dup2(b1.x), dup2(b1.y), dup2(b1.z), dup2(b1.w)};
#pragma unroll
            for (int i = 0; i < 4; i++)
#pragma unroll
                for (int j = 0; j < 8; j++)
                    c[i][j] = ffma2(a[i], bd[j], c[i][j]);
        }
        if (step + 1 < STEPS) STORESMEM_B((step + 1) & 1);
        __syncthreads();
    }
#undef LOADREGS_B
#undef STORESMEM_B

    // epilogue: write out
#pragma unroll
    for (int i = 0; i < 4; i++) {
        float2 f[8];
#pragma unroll
        for (int j = 0; j < 8; j++) f[j] = unpk(c[i][j]);
        const int m = m0 + ty * 8 + i * 2;
        float* op = out + (size_t)m * N2 + n0 + tx * 8;
        *(float4*)op             = make_float4(f[0].x, f[1].x, f[2].x, f[3].x);
        *(float4*)(op + 4)       = make_float4(f[4].x, f[5].x, f[6].x, f[7].x);
        *(float4*)(op + N2)      = make_float4(f[0].y, f[1].y, f[2].y, f[3].y);
        *(float4*)(op + N2 + 4)  = make_float4(f[4].y, f[5].y, f[6].y, f[7].y);
    }
}

// ---------------------------------------------------------------------------
// Host launcher. Inputs (metadata order): x, gate_qweight, gate_scales,
// gate_qzeros, up_qweight, up_scales, up_qzeros, down_qweight, down_scales,
// down_qzeros, groupsize(=128, ignored).
// ---------------------------------------------------------------------------
extern "C" void kernel_launch(void* const* d_in, const int* in_sizes, int n_in,
                              void* d_out, int out_size)
{
    (void)in_sizes; (void)n_in; (void)out_size;
    const float* x   = (const float*)d_in[0];
    const int*   gqw = (const int*)  d_in[1];
    const float* gsc = (const float*)d_in[2];
    const int*   gqz = (const int*)  d_in[3];
    const int*   uqw = (const int*)  d_in[4];
    const float* usc = (const float*)d_in[5];
    const int*   uqz = (const int*)  d_in[6];
    const int*   dqw = (const int*)  d_in[7];
    const float* dsc = (const float*)d_in[8];
    const int*   dqz = (const int*)  d_in[9];
    float* out = (float*)d_out;

    dim3 gridA(N1 / 64, M_TOT / 128);     // 172 x 32
    gateup_kernel<<<gridA, 256>>>(x, gqw, gsc, gqz, uqw, usc, uqz);

    dim3 gridB(N2 / 128, M_TOT / 128);    // 32 x 32
    down_kernel<<<gridB, 256>>>(dqw, dsc, dqz, out);
}

// round 6
// speedup vs baseline: 1.0007x; 1.0007x over previous
#include <cuda_runtime.h>
#include <stdint.h>

typedef unsigned long long ull;

// ---------------------------------------------------------------------------
// Blackwell packed-fp32 helpers (FFMA2: 2x fp32 FMA per instruction)
// ---------------------------------------------------------------------------
__device__ __forceinline__ ull ffma2(ull a, ull b, ull c) {
    ull d;
    asm("fma.rn.f32x2 %0, %1, %2, %3;" : "=l"(d) : "l"(a), "l"(b), "l"(c));
    return d;
}
__device__ __forceinline__ ull dup2(float x) {
    ull d;
    asm("mov.b64 %0, {%1, %1};" : "=l"(d) : "f"(x));
    return d;
}
__device__ __forceinline__ float2 unpk(ull v) {
    float2 f;
    asm("mov.b64 {%0, %1}, %2;" : "=f"(f.x), "=f"(f.y) : "l"(v));
    return f;
}
__device__ __forceinline__ float silu_f(float g) {
    return g / (1.f + __expf(-g));
}

#define M_TOT 4096
#define K1    4096
#define N1    11008
#define N2    4096

// intermediate h = silu(gate) * up, fp32, 4096 x 11008 (~180 MB scratch)
__device__ float g_hbuf[(size_t)M_TOT * (size_t)N1];

// ---------------------------------------------------------------------------
// Kernel A: gate+up GEMM (M=4096, K=4096, N=11008) + silu*mul -> g_hbuf
// Block tile: 128(M) x 64(N) x 8(K). 256 threads. Thread tile: 8(M)x4(N) for
// BOTH gate and up. Accumulators packed 2-wide along M (f32x2).
// ---------------------------------------------------------------------------
__global__ __launch_bounds__(256)
void gateup_kernel(const float* __restrict__ x,
                   const int*   __restrict__ gqw, const float* __restrict__ gsc, const int* __restrict__ gqz,
                   const int*   __restrict__ uqw, const float* __restrict__ usc, const int* __restrict__ uqz)
{
    __shared__ float As[2][8][132];   // As[k][m], padded stride (conflict-free)
    __shared__ float Bg[2][8][68];    // dequantized gate tile [k][n]
    __shared__ float Bu[2][8][68];    // dequantized up tile   [k][n]

    const int tid = threadIdx.x;
    const int tx  = tid & 15;         // n-quad  (0..15) -> n = tx*4
    const int ty  = tid >> 4;         // m-octet (0..15) -> m = ty*8
    const int n0  = blockIdx.x * 64;
    const int m0  = blockIdx.y * 128;

    // A-tile loader: 256 threads * float4 = 128 rows x 8 k
    const int am = tid >> 1, aq = tid & 1;
    const float* xp = x + (size_t)(m0 + am) * K1 + aq * 4;

    // B-tile loader: 128 threads per matrix, 64 cols x 2 k-halves
    const int bn   = tid & 63;
    const int bh   = (tid >> 6) & 1;
    const int bmat = tid >> 7;
    const int gn   = n0 + bn;
    const int*   qw = bmat ? uqw : gqw;
    const float* sc = bmat ? usc : gsc;
    const int*   qz = bmat ? uqz : gqz;
    float* Bbase = bmat ? &Bu[0][0][0] : &Bg[0][0][0];

    ull cg[4][4], cu[4][4];
#pragma unroll
    for (int i = 0; i < 4; i++)
#pragma unroll
        for (int j = 0; j < 4; j++) { cg[i][j] = 0ull; cu[i][j] = 0ull; }

    float4 av; uint32_t qv, zv; float sv;

#define LOADREGS_A(k0) do {                                                      \
    av = *(const float4*)(xp + (k0));                                            \
    qv = (uint32_t)__ldg(qw + (size_t)((k0) >> 3) * N1 + gn);                    \
    sv = __ldg(sc + (size_t)((k0) >> 7) * N1 + gn);                              \
    zv = (uint32_t)__ldg(qz + (size_t)((k0) >> 7) * (N1 / 8) + (gn >> 3));       \
} while (0)

#define STORESMEM_A(st) do {                                                     \
    As[st][aq*4+0][am] = av.x; As[st][aq*4+1][am] = av.y;                        \
    As[st][aq*4+2][am] = av.z; As[st][aq*4+3][am] = av.w;                        \
    float zt = ((float)((zv >> ((gn & 7) * 4)) & 15) + 1.f) * sv;                \
    uint32_t qs = qv >> (bh * 16);                                               \
    float* Bp = Bbase + (st) * (8 * 68) + (bh * 4) * 68 + bn;                    \
    Bp[0*68] = (float)( qs        & 15) * sv - zt;                               \
    Bp[1*68] = (float)((qs >>  4) & 15) * sv - zt;                               \
    Bp[2*68] = (float)((qs >>  8) & 15) * sv - zt;                               \
    Bp[3*68] = (float)((qs >> 12) & 15) * sv - zt;                               \
} while (0)

    LOADREGS_A(0);
    STORESMEM_A(0);
    __syncthreads();

    const int STEPS = K1 / 8;   // 512
    for (int step = 0; step < STEPS; ++step) {
        const int cur = step & 1;
        if (step + 1 < STEPS) LOADREGS_A((step + 1) * 8);

#pragma unroll
        for (int kk = 0; kk < 8; kk++) {
            ull a[4];
#pragma unroll
            for (int i = 0; i < 4; i++)
                a[i] = *(const ull*)&As[cur][kk][ty * 8 + 2 * i];
            float4 bg4 = *(const float4*)&Bg[cur][kk][tx * 4];
            float4 bu4 = *(const float4*)&Bu[cur][kk][tx * 4];
            ull bgd[4] = {dup2(bg4.x), dup2(bg4.y), dup2(bg4.z), dup2(bg4.w)};
            ull bud[4] = {dup2(bu4.x), dup2(bu4.y), dup2(bu4.z), dup2(bu4.w)};
#pragma unroll
            for (int i = 0; i < 4; i++)
#pragma unroll
                for (int j = 0; j < 4; j++) {
                    cg[i][j] = ffma2(a[i], bgd[j], cg[i][j]);
                    cu[i][j] = ffma2(a[i], bud[j], cu[i][j]);
                }
        }
        if (step + 1 < STEPS) STORESMEM_A((step + 1) & 1);
        __syncthreads();
    }
#undef LOADREGS_A
#undef STORESMEM_A

    // epilogue: h = silu(g) * u
#pragma unroll
    for (int i = 0; i < 4; i++) {
        float r0[4], r1[4];
#pragma unroll
        for (int j = 0; j < 4; j++) {
            float2 g2 = unpk(cg[i][j]);
            float2 u2 = unpk(cu[i][j]);
            r0[j] = silu_f(g2.x) * u2.x;
            r1[j] = silu_f(g2.y) * u2.y;
        }
        const int m = m0 + ty * 8 + i * 2;
        float* hp = g_hbuf + (size_t)m * N1 + n0 + tx * 4;
        *(float4*)hp         = make_float4(r0[0], r0[1], r0[2], r0[3]);
        *(float4*)(hp + N1)  = make_float4(r1[0], r1[1], r1[2], r1[3]);
    }
}

// ---------------------------------------------------------------------------
// Kernel B: down GEMM out = h @ Wd  (M=4096, K=11008, N=4096)
// Block tile: 128(M) x 128(N) x 8(K). 256 threads. Thread tile: 8(M)x8(N).
// ---------------------------------------------------------------------------
__global__ __launch_bounds__(256)
void down_kernel(const int* __restrict__ dqw, const float* __restrict__ dsc,
                 const int* __restrict__ dqz, float* __restrict__ out)
{
    __shared__ float As[2][8][132];
    __shared__ float Bs[2][8][132];

    const int tid = threadIdx.x;
    const int tx  = tid & 15;         // n = tx*8
    const int ty  = tid >> 4;         // m = ty*8
    const int n0  = blockIdx.x * 128;
    const int m0  = blockIdx.y * 128;

    const int am = tid >> 1, aq = tid & 1;
    const float* hp = g_hbuf + (size_t)(m0 + am) * N1 + aq * 4;

    const int bn = tid & 127;
    const int bh = tid >> 7;
    const int gn = n0 + bn;

    ull c[4][8];
#pragma unroll
    for (int i = 0; i < 4; i++)
#pragma unroll
        for (int j = 0; j < 8; j++) c[i][j] = 0ull;

    float4 av; uint32_t qv, zv; float sv;

#define LOADREGS_B(k0) do {                                                      \
    av = *(const float4*)(hp + (k0));                                            \
    qv = (uint32_t)__ldg(dqw + (size_t)((k0) >> 3) * N2 + gn);                   \
    sv = __ldg(dsc + (size_t)((k0) >> 7) * N2 + gn);                             \
    zv = (uint32_t)__ldg(dqz + (size_t)((k0) >> 7) * (N2 / 8) + (gn >> 3));      \
} while (0)

#define STORESMEM_B(st) do {                                                     \
    As[st][aq*4+0][am] = av.x; As[st][aq*4+1][am] = av.y;                        \
    As[st][aq*4+2][am] = av.z; As[st][aq*4+3][am] = av.w;                        \
    float zt = ((float)((zv >> ((gn & 7) * 4)) & 15) + 1.f) * sv;                \
    uint32_t qs = qv >> (bh * 16);                                               \
    Bs[st][bh*4+0][bn] = (float)( qs        & 15) * sv - zt;                     \
    Bs[st][bh*4+1][bn] = (float)((qs >>  4) & 15) * sv - zt;                     \
    Bs[st][bh*4+2][bn] = (float)((qs >>  8) & 15) * sv - zt;                     \
    Bs[st][bh*4+3][bn] = (float)((qs >> 12) & 15) * sv - zt;                     \
} while (0)

    LOADREGS_B(0);
    STORESMEM_B(0);
    __syncthreads();

    const int STEPS = N1 / 8;   // 1376 (K dim of this GEMM is 11008)
    for (int step = 0; step < STEPS; ++step) {
        const int cur = step & 1;
        if (step + 1 < STEPS) LOADREGS_B((step + 1) * 8);

#pragma unroll
        for (int kk = 0; kk < 8; kk++) {
            ull a[4];
#pragma unroll
            for (int i = 0; i < 4; i++)
                a[i] = *(const ull*)&As[cur][kk][ty * 8 + 2 * i];
            float4 b0 = *(const float4*)&Bs[cur][kk][tx * 8];
            float4 b1 = *(const float4*)&Bs[cur][kk][tx * 8 + 4];
            ull bd[8] = {dup2(b0.x), dup2(b0.y), dup2(b0.z), dup2(b0.w),
                         dup2(b1.x), dup2(b1.y), dup2(b1.z), dup2(b1.w)};
#pragma unroll
            for (int i = 0; i < 4; i++)
#pragma unroll
                for (int j = 0; j < 8; j++)
                    c[i][j] = ffma2(a[i], bd[j], c[i][j]);
        }
        if (step + 1 < STEPS) STORESMEM_B((step + 1) & 1);
        __syncthreads();
    }
#undef LOADREGS_B
#undef STORESMEM_B

    // epilogue: write out
#pragma unroll
    for (int i = 0; i < 4; i++) {
        float2 f[8];
#pragma unroll
        for (int j = 0; j < 8; j++) f[j] = unpk(c[i][j]);
        const int m = m0 + ty * 8 + i * 2;
        float* op = out + (size_t)m * N2 + n0 + tx * 8;
        *(float4*)op             = make_float4(f[0].x, f[1].x, f[2].x, f[3].x);
        *(float4*)(op + 4)       = make_float4(f[4].x, f[5].x, f[6].x, f[7].x);
        *(float4*)(op + N2)      = make_float4(f[0].y, f[1].y, f[2].y, f[3].y);
        *(float4*)(op + N2 + 4)  = make_float4(f[4].y, f[5].y, f[6].y, f[7].y);
    }
}

// ---------------------------------------------------------------------------
// Host launcher. Inputs (metadata order): x, gate_qweight, gate_scales,
// gate_qzeros, up_qweight, up_scales, up_qzeros, down_qweight, down_scales,
// down_qzeros, groupsize(=128, ignored).
// ---------------------------------------------------------------------------
extern "C" void kernel_launch(void* const* d_in, const int* in_sizes, int n_in,
                              void* d_out, int out_size)
{
    (void)in_sizes; (void)n_in; (void)out_size;
    const float* x   = (const float*)d_in[0];
    const int*   gqw = (const int*)  d_in[1];
    const float* gsc = (const float*)d_in[2];
    const int*   gqz = (const int*)  d_in[3];
    const int*   uqw = (const int*)  d_in[4];
    const float* usc = (const float*)d_in[5];
    const int*   uqz = (const int*)  d_in[6];
    const int*   dqw = (const int*)  d_in[7];
    const float* dsc = (const float*)d_in[8];
    const int*   dqz = (const int*)  d_in[9];
    float* out = (float*)d_out;

    dim3 gridA(N1 / 64, M_TOT / 128);     // 172 x 32
    gateup_kernel<<<gridA, 256>>>(x, gqw, gsc, gqz, uqw, usc, uqz);

    dim3 gridB(N2 / 128, M_TOT / 128);    // 32 x 32
    down_kernel<<<gridB, 256>>>(dqw, dsc, dqz, out);
}

// round 7
// speedup vs baseline: 1.0030x; 1.0023x over previous
#include <cuda_runtime.h>
#include <stdint.h>

typedef unsigned long long ull;

// ---------------------------------------------------------------------------
// Blackwell packed-fp32 helpers (FFMA2: 2x fp32 FMA per instruction)
// ---------------------------------------------------------------------------
__device__ __forceinline__ ull ffma2(ull a, ull b, ull c) {
    ull d;
    asm("fma.rn.f32x2 %0, %1, %2, %3;" : "=l"(d) : "l"(a), "l"(b), "l"(c));
    return d;
}
__device__ __forceinline__ ull dup2(float x) {
    ull d;
    asm("mov.b64 %0, {%1, %1};" : "=l"(d) : "f"(x));
    return d;
}
__device__ __forceinline__ float2 unpk(ull v) {
    float2 f;
    asm("mov.b64 {%0, %1}, %2;" : "=f"(f.x), "=f"(f.y) : "l"(v));
    return f;
}
__device__ __forceinline__ float silu_f(float g) {
    return g / (1.f + __expf(-g));
}

#define M_TOT 4096
#define K1    4096
#define N1    11008
#define N2    4096

// intermediate h = silu(gate) * up, fp32, 4096 x 11008 (~180 MB scratch)
__device__ float g_hbuf[(size_t)M_TOT * (size_t)N1];

// ---------------------------------------------------------------------------
// Kernel A: gate+up GEMM (M=4096, K=4096, N=11008) + silu*mul -> g_hbuf
// Block tile: 128(M) x 64(N) x 8(K). 256 threads. Thread tile: 8(M)x4(N) for
// BOTH gate and up. Accumulators packed 2-wide along M (f32x2).
// ---------------------------------------------------------------------------
__global__ __launch_bounds__(256)
void gateup_kernel(const float* __restrict__ x,
                   const int*   __restrict__ gqw, const float* __restrict__ gsc, const int* __restrict__ gqz,
                   const int*   __restrict__ uqw, const float* __restrict__ usc, const int* __restrict__ uqz)
{
    __shared__ float As[2][8][132];   // As[k][m], padded stride (conflict-free)
    __shared__ float Bg[2][8][68];    // dequantized gate tile [k][n]
    __shared__ float Bu[2][8][68];    // dequantized up tile   [k][n]

    const int tid = threadIdx.x;
    const int tx  = tid & 15;         // n-quad  (0..15) -> n = tx*4
    const int ty  = tid >> 4;         // m-octet (0..15) -> m = ty*8
    const int n0  = blockIdx.x * 64;
    const int m0  = blockIdx.y * 128;

    // A-tile loader: 256 threads * float4 = 128 rows x 8 k
    const int am = tid >> 1, aq = tid & 1;
    const float* xp = x + (size_t)(m0 + am) * K1 + aq * 4;

    // B-tile loader: 128 threads per matrix, 64 cols x 2 k-halves
    const int bn   = tid & 63;
    const int bh   = (tid >> 6) & 1;
    const int bmat = tid >> 7;
    const int gn   = n0 + bn;
    const int*   qw = bmat ? uqw : gqw;
    const float* sc = bmat ? usc : gsc;
    const int*   qz = bmat ? uqz : gqz;
    float* Bbase = bmat ? &Bu[0][0][0] : &Bg[0][0][0];

    ull cg[4][4], cu[4][4];
#pragma unroll
    for (int i = 0; i < 4; i++)
#pragma unroll
        for (int j = 0; j < 4; j++) { cg[i][j] = 0ull; cu[i][j] = 0ull; }

    float4 av; uint32_t qv, zv; float sv;

#define LOADREGS_A(k0) do {                                                      \
    av = *(const float4*)(xp + (k0));                                            \
    qv = (uint32_t)__ldg(qw + (size_t)((k0) >> 3) * N1 + gn);                    \
    sv = __ldg(sc + (size_t)((k0) >> 7) * N1 + gn);                              \
    zv = (uint32_t)__ldg(qz + (size_t)((k0) >> 7) * (N1 / 8) + (gn >> 3));       \
} while (0)

#define STORESMEM_A(st) do {                                                     \
    As[st][aq*4+0][am] = av.x; As[st][aq*4+1][am] = av.y;                        \
    As[st][aq*4+2][am] = av.z; As[st][aq*4+3][am] = av.w;                        \
    float zt = ((float)((zv >> ((gn & 7) * 4)) & 15) + 1.f) * sv;                \
    uint32_t qs = qv >> (bh * 16);                                               \
    float* Bp = Bbase + (st) * (8 * 68) + (bh * 4) * 68 + bn;                    \
    Bp[0*68] = (float)( qs        & 15) * sv - zt;                               \
    Bp[1*68] = (float)((qs >>  4) & 15) * sv - zt;                               \
    Bp[2*68] = (float)((qs >>  8) & 15) * sv - zt;                               \
    Bp[3*68] = (float)((qs >> 12) & 15) * sv - zt;                               \
} while (0)

    LOADREGS_A(0);
    STORESMEM_A(0);
    __syncthreads();

    const int STEPS = K1 / 8;   // 512
    for (int step = 0; step < STEPS; ++step) {
        const int cur = step & 1;
        if (step + 1 < STEPS) LOADREGS_A((step + 1) * 8);

#pragma unroll
        for (int kk = 0; kk < 8; kk++) {
            ull a[4];
#pragma unroll
            for (int i = 0; i < 4; i++)
                a[i] = *(const ull*)&As[cur][kk][ty * 8 + 2 * i];
            float4 bg4 = *(const float4*)&Bg[cur][kk][tx * 4];
            float4 bu4 = *(const float4*)&Bu[cur][kk][tx * 4];
            ull bgd[4] = {dup2(bg4.x), dup2(bg4.y), dup2(bg4.z), dup2(bg4.w)};
            ull bud[4] = {dup2(bu4.x), dup2(bu4.y), dup2(bu4.z), dup2(bu4.w)};
#pragma unroll
            for (int i = 0; i < 4; i++)
#pragma unroll
                for (int j = 0; j < 4; j++) {
                    cg[i][j] = ffma2(a[i], bgd[j], cg[i][j]);
                    cu[i][j] = ffma2(a[i], bud[j], cu[i][j]);
                }
        }
        if (step + 1 < STEPS) STORESMEM_A((step + 1) & 1);
        __syncthreads();
    }
#undef LOADREGS_A
#undef STORESMEM_A

    // epilogue: h = silu(g) * u
#pragma unroll
    for (int i = 0; i < 4; i++) {
        float r0[4], r1[4];
#pragma unroll
        for (int j = 0; j < 4; j++) {
            float2 g2 = unpk(cg[i][j]);
            float2 u2 = unpk(cu[i][j]);
            r0[j] = silu_f(g2.x) * u2.x;
            r1[j] = silu_f(g2.y) * u2.y;
        }
        const int m = m0 + ty * 8 + i * 2;
        float* hp = g_hbuf + (size_t)m * N1 + n0 + tx * 4;
        *(float4*)hp         = make_float4(r0[0], r0[1], r0[2], r0[3]);
        *(float4*)(hp + N1)  = make_float4(r1[0], r1[1], r1[2], r1[3]);
    }
}

// ---------------------------------------------------------------------------
// Kernel B: down GEMM out = h @ Wd  (M=4096, K=11008, N=4096)
// Block tile: 128(M) x 128(N) x 8(K). 256 threads. Thread tile: 8(M)x8(N).
// ---------------------------------------------------------------------------
__global__ __launch_bounds__(256)
void down_kernel(const int* __restrict__ dqw, const float* __restrict__ dsc,
                 const int* __restrict__ dqz, float* __restrict__ out)
{
    __shared__ float As[2][8][132];
    __shared__ float Bs[2][8][132];

    const int tid = threadIdx.x;
    const int tx  = tid & 15;         // n = tx*8
    const int ty  = tid >> 4;         // m = ty*8
    const int n0  = blockIdx.x * 128;
    const int m0  = blockIdx.y * 128;

    const int am = tid >> 1, aq = tid & 1;
    const float* hp = g_hbuf + (size_t)(m0 + am) * N1 + aq * 4;

    const int bn = tid & 127;
    const int bh = tid >> 7;
    const int gn = n0 + bn;

    ull c[4][8];
#pragma unroll
    for (int i = 0; i < 4; i++)
#pragma unroll
        for (int j = 0; j < 8; j++) c[i][j] = 0ull;

    float4 av; uint32_t qv, zv; float sv;

#define LOADREGS_B(k0) do {                                                      \
    av = *(const float4*)(hp + (k0));                                            \
    qv = (uint32_t)__ldg(dqw + (size_t)((k0) >> 3) * N2 + gn);                   \
    sv = __ldg(dsc + (size_t)((k0) >> 7) * N2 + gn);                             \
    zv = (uint32_t)__ldg(dqz + (size_t)((k0) >> 7) * (N2 / 8) + (gn >> 3));      \
} while (0)

#define STORESMEM_B(st) do {                                                     \
    As[st][aq*4+0][am] = av.x; As[st][aq*4+1][am] = av.y;                        \
    As[st][aq*4+2][am] = av.z; As[st][aq*4+3][am] = av.w;                        \
    float zt = ((float)((zv >> ((gn & 7) * 4)) & 15) + 1.f) * sv;                \
    uint32_t qs = qv >> (bh * 16);                                               \
    Bs[st][bh*4+0][bn] = (float)( qs        & 15) * sv - zt;                     \
    Bs[st][bh*4+1][bn] = (float)((qs >>  4) & 15) * sv - zt;                     \
    Bs[st][bh*4+2][bn] = (float)((qs >>  8) & 15) * sv - zt;                     \
    Bs[st][bh*4+3][bn] = (float)((qs >> 12) & 15) * sv - zt;                     \
} while (0)

    LOADREGS_B(0);
    STORESMEM_B(0);
    __syncthreads();

    const int STEPS = N1 / 8;   // 1376 (K dim of this GEMM is 11008)
    for (int step = 0; step < STEPS; ++step) {
        const int cur = step & 1;
        if (step + 1 < STEPS) LOADREGS_B((step + 1) * 8);

#pragma unroll
        for (int kk = 0; kk < 8; kk++) {
            ull a[4];
#pragma unroll
            for (int i = 0; i < 4; i++)
                a[i] = *(const ull*)&As[cur][kk][ty * 8 + 2 * i];
            float4 b0 = *(const float4*)&Bs[cur][kk][tx * 8];
            float4 b1 = *(const float4*)&Bs[cur][kk][tx * 8 + 4];
            ull bd[8] = {dup2(b0.x), dup2(b0.y), dup2(b0.z), dup2(b0.w),
                         dup2(b1.x), dup2(b1.y), dup2(b1.z), dup2(b1.w)};
#pragma unroll
            for (int i = 0; i < 4; i++)
#pragma unroll
                for (int j = 0; j < 8; j++)
                    c[i][j] = ffma2(a[i], bd[j], c[i][j]);
        }
        if (step + 1 < STEPS) STORESMEM_B((step + 1) & 1);
        __syncthreads();
    }
#undef LOADREGS_B
#undef STORESMEM_B

    // epilogue: write out
#pragma unroll
    for (int i = 0; i < 4; i++) {
        float2 f[8];
#pragma unroll
        for (int j = 0; j < 8; j++) f[j] = unpk(c[i][j]);
        const int m = m0 + ty * 8 + i * 2;
        float* op = out + (size_t)m * N2 + n0 + tx * 8;
        *(float4*)op             = make_float4(f[0].x, f[1].x, f[2].x, f[3].x);
        *(float4*)(op + 4)       = make_float4(f[4].x, f[5].x, f[6].x, f[7].x);
        *(float4*)(op + N2)      = make_float4(f[0].y, f[1].y, f[2].y, f[3].y);
        *(float4*)(op + N2 + 4)  = make_float4(f[4].y, f[5].y, f[6].y, f[7].y);
    }
}

// ---------------------------------------------------------------------------
// Host launcher. Inputs (metadata order): x, gate_qweight, gate_scales,
// gate_qzeros, up_qweight, up_scales, up_qzeros, down_qweight, down_scales,
// down_qzeros, groupsize(=128, ignored).
// ---------------------------------------------------------------------------
extern "C" void kernel_launch(void* const* d_in, const int* in_sizes, int n_in,
                              void* d_out, int out_size)
{
    (void)in_sizes; (void)n_in; (void)out_size;
    const float* x   = (const float*)d_in[0];
    const int*   gqw = (const int*)  d_in[1];
    const float* gsc = (const float*)d_in[2];
    const int*   gqz = (const int*)  d_in[3];
    const int*   uqw = (const int*)  d_in[4];
    const float* usc = (const float*)d_in[5];
    const int*   uqz = (const int*)  d_in[6];
    const int*   dqw = (const int*)  d_in[7];
    const float* dsc = (const float*)d_in[8];
    const int*   dqz = (const int*)  d_in[9];
    float* out = (float*)d_out;

    dim3 gridA(N1 / 64, M_TOT / 128);     // 172 x 32
    gateup_kernel<<<gridA, 256>>>(x, gqw, gsc, gqz, uqw, usc, uqz);

    dim3 gridB(N2 / 128, M_TOT / 128);    // 32 x 32
    down_kernel<<<gridB, 256>>>(dqw, dsc, dqz, out);
}

// round 9
// speedup vs baseline: 2.7089x; 2.7008x over previous
#include <cuda_runtime.h>
#include <stdint.h>

typedef unsigned int u32;

#define M_TOT 4096
#define K1    4096
#define N1    11008
#define N2    4096
#define PADK  20          // 16 k-floats + 4 pad (conflict-free fragment LDS)

// intermediate h = silu(gate)*up, fp32 (tf32-converted at down-kernel tile load)
__device__ float g_h[(size_t)M_TOT * (size_t)N1];

// ---------------------------------------------------------------------------
// helpers
// ---------------------------------------------------------------------------
static __device__ __forceinline__ u32 tf32u(float x){
    u32 r; asm("cvt.rna.tf32.f32 %0, %1;" : "=r"(r) : "f"(x)); return r;
}
static __device__ __forceinline__ float silu_f(float g){ return g / (1.f + __expf(-g)); }

// D += A(16x8) * B(8x8), tf32 operands, fp32 accum
static __device__ __forceinline__ void mma8(float* d, const u32* a, const u32* b){
    asm volatile("mma.sync.aligned.m16n8k8.row.col.f32.tf32.tf32.f32 "
        "{%0,%1,%2,%3}, {%4,%5,%6,%7}, {%8,%9}, {%0,%1,%2,%3};"
        : "+f"(d[0]), "+f"(d[1]), "+f"(d[2]), "+f"(d[3])
        : "r"(a[0]), "r"(a[1]), "r"(a[2]), "r"(a[3]), "r"(b[0]), "r"(b[1]));
}

// dequant one packed int32 (8 int4 along k) -> 8 tf32 floats, contiguous
static __device__ __forceinline__ void deq8(u32 q, float s, float nzt, float* dst){
    float4 a, b;
    a.x = __uint_as_float(tf32u(fmaf((float)( q        & 15), s, nzt)));
    a.y = __uint_as_float(tf32u(fmaf((float)((q >>  4) & 15), s, nzt)));
    a.z = __uint_as_float(tf32u(fmaf((float)((q >>  8) & 15), s, nzt)));
    a.w = __uint_as_float(tf32u(fmaf((float)((q >> 12) & 15), s, nzt)));
    b.x = __uint_as_float(tf32u(fmaf((float)((q >> 16) & 15), s, nzt)));
    b.y = __uint_as_float(tf32u(fmaf((float)((q >> 20) & 15), s, nzt)));
    b.z = __uint_as_float(tf32u(fmaf((float)((q >> 24) & 15), s, nzt)));
    b.w = __uint_as_float(tf32u(fmaf((float)((q >> 28) & 15), s, nzt)));
    *(float4*)dst = a; *(float4*)(dst + 4) = b;
}
static __device__ __forceinline__ float4 cvt4(float4 v){
    float4 r;
    r.x = __uint_as_float(tf32u(v.x)); r.y = __uint_as_float(tf32u(v.y));
    r.z = __uint_as_float(tf32u(v.z)); r.w = __uint_as_float(tf32u(v.w));
    return r;
}

// ---------------------------------------------------------------------------
// Kernel A: fused gate+up GEMM (M=4096,K=4096,N=11008) + silu*mul -> g_h
// CTA 128x128, BK=16, double-buffered smem, 8 warps = 2(M) x 4(N),
// warp tile 64(M) x 32(N) per matrix (gate AND up share the A fragments).
// ---------------------------------------------------------------------------
#define GU_SMEM (3 * 2 * 128 * PADK * 4)

__global__ __launch_bounds__(256, 1)
void gateup_mma(const float* __restrict__ x,
                const int* __restrict__ gqw, const float* __restrict__ gsc, const int* __restrict__ gqz,
                const int* __restrict__ uqw, const float* __restrict__ usc, const int* __restrict__ uqz)
{
    extern __shared__ float sm[];
    float* AsS = sm;                       // [2][128][PADK]
    float* BgS = sm + 2 * 128 * PADK;      // [2][128][PADK]
    float* BuS = BgS + 2 * 128 * PADK;

    const int tid = threadIdx.x, wid = tid >> 5, lid = tid & 31;
    const int warpM = wid >> 2, warpN = wid & 3;
    const int n0 = blockIdx.x * 128, m0 = blockIdx.y * 128;
    const int r = lid >> 2, c = lid & 3;

    // A loader: 2 chunks of float4 per thread (128 rows x 16 k)
    const int arow0 = tid >> 2,       acq = tid & 3;
    const int arow1 = 64 + (tid >> 2);
    const float* xp0 = x + (size_t)(m0 + arow0) * K1 + acq * 4;
    const float* xp1 = x + (size_t)(m0 + arow1) * K1 + acq * 4;

    // weight loader: one packed word per matrix per stage
    const int bn = tid & 127, kh = tid >> 7;
    const int gcol = n0 + bn, zsh = (bn & 7) * 4;

    float accG[4][4][4], accU[4][4][4];
#pragma unroll
    for (int i = 0; i < 4; i++)
#pragma unroll
        for (int j = 0; j < 4; j++)
#pragma unroll
            for (int k = 0; k < 4; k++){ accG[i][j][k] = 0.f; accU[i][j][k] = 0.f; }

    float4 xa0, xa1; u32 gq, uq, gz, uz; float gs, us;

#define LDR_GU(kt) do {                                                          \
    xa0 = *(const float4*)(xp0 + (kt) * 16);                                     \
    xa1 = *(const float4*)(xp1 + (kt) * 16);                                     \
    size_t wr = (size_t)((kt) * 2 + kh) * N1 + gcol;                             \
    gq = __ldg((const u32*)gqw + wr);                                            \
    uq = __ldg((const u32*)uqw + wr);                                            \
    int g = (kt) >> 3;                                                           \
    gs = __ldg(gsc + (size_t)g * N1 + gcol);                                     \
    us = __ldg(usc + (size_t)g * N1 + gcol);                                     \
    gz = __ldg((const u32*)gqz + (size_t)g * (N1/8) + (gcol >> 3));              \
    uz = __ldg((const u32*)uqz + (size_t)g * (N1/8) + (gcol >> 3));              \
} while (0)

#define STR_GU(st) do {                                                          \
    float* a = AsS + (st) * 128 * PADK;                                          \
    *(float4*)(a + arow0 * PADK + acq * 4) = cvt4(xa0);                          \
    *(float4*)(a + arow1 * PADK + acq * 4) = cvt4(xa1);                          \
    float* bg = BgS + (st) * 128 * PADK + bn * PADK + kh * 8;                    \
    float s = gs, nzt = -((float)(((gz >> zsh) & 15) + 1)) * s;                  \
    deq8(gq, s, nzt, bg);                                                        \
    float* bu = BuS + (st) * 128 * PADK + bn * PADK + kh * 8;                    \
    s = us; nzt = -((float)(((uz >> zsh) & 15) + 1)) * s;                        \
    deq8(uq, s, nzt, bu);                                                        \
} while (0)

    LDR_GU(0);
    STR_GU(0);
    __syncthreads();

    const int NK = K1 / 16;   // 256
    for (int kt = 0; kt < NK; ++kt){
        const int cur = kt & 1;
        if (kt + 1 < NK) LDR_GU(kt + 1);

        const float* Ab = AsS + cur * 128 * PADK + (warpM * 64 + r) * PADK + c;
        const float* Gb = BgS + cur * 128 * PADK + (warpN * 32 + r) * PADK + c;
        const float* Ub = BuS + cur * 128 * PADK + (warpN * 32 + r) * PADK + c;
#pragma unroll
        for (int k8 = 0; k8 < 16; k8 += 8){
            u32 af[4][4];
#pragma unroll
            for (int mt = 0; mt < 4; mt++){
                const float* p = Ab + mt * 16 * PADK + k8;
                af[mt][0] = __float_as_uint(p[0]);
                af[mt][1] = __float_as_uint(p[8 * PADK]);
                af[mt][2] = __float_as_uint(p[4]);
                af[mt][3] = __float_as_uint(p[8 * PADK + 4]);
            }
            u32 bf[4][2], uf[4][2];
#pragma unroll
            for (int nt = 0; nt < 4; nt++){
                const float* p = Gb + nt * 8 * PADK + k8;
                bf[nt][0] = __float_as_uint(p[0]); bf[nt][1] = __float_as_uint(p[4]);
                const float* q = Ub + nt * 8 * PADK + k8;
                uf[nt][0] = __float_as_uint(q[0]); uf[nt][1] = __float_as_uint(q[4]);
            }
#pragma unroll
            for (int mt = 0; mt < 4; mt++)
#pragma unroll
                for (int nt = 0; nt < 4; nt++){
                    mma8(accG[mt][nt], af[mt], bf[nt]);
                    mma8(accU[mt][nt], af[mt], uf[nt]);
                }
        }

        if (kt + 1 < NK) STR_GU((kt + 1) & 1);
        __syncthreads();
    }
#undef LDR_GU
#undef STR_GU

    // epilogue: h = silu(g) * u
#pragma unroll
    for (int mt = 0; mt < 4; mt++)
#pragma unroll
        for (int nt = 0; nt < 4; nt++){
            const int row = m0 + warpM * 64 + mt * 16 + r;
            const int col = n0 + warpN * 32 + nt * 8 + c * 2;
            float* hp = g_h + (size_t)row * N1 + col;
            const float* a = accG[mt][nt]; const float* b = accU[mt][nt];
            float2 v0 = make_float2(silu_f(a[0]) * b[0], silu_f(a[1]) * b[1]);
            float2 v1 = make_float2(silu_f(a[2]) * b[2], silu_f(a[3]) * b[3]);
            *(float2*)hp            = v0;
            *(float2*)(hp + 8 * N1) = v1;
        }
}

// ---------------------------------------------------------------------------
// Kernel B: down GEMM out = h @ Wd (M=4096, K=11008, N=4096)
// Same structure, single B matrix.
// ---------------------------------------------------------------------------
#define DN_SMEM (2 * 2 * 128 * PADK * 4)

__global__ __launch_bounds__(256, 1)
void down_mma(const int* __restrict__ dqw, const float* __restrict__ dsc,
              const int* __restrict__ dqz, float* __restrict__ out)
{
    extern __shared__ float sm[];
    float* AsS = sm;                       // [2][128][PADK]
    float* BsS = sm + 2 * 128 * PADK;

    const int tid = threadIdx.x, wid = tid >> 5, lid = tid & 31;
    const int warpM = wid >> 2, warpN = wid & 3;
    const int n0 = blockIdx.x * 128, m0 = blockIdx.y * 128;
    const int r = lid >> 2, c = lid & 3;

    const int arow0 = tid >> 2,       acq = tid & 3;
    const int arow1 = 64 + (tid >> 2);
    const float* hp0 = g_h + (size_t)(m0 + arow0) * N1 + acq * 4;
    const float* hp1 = g_h + (size_t)(m0 + arow1) * N1 + acq * 4;

    const int bn = tid & 127, kh = tid >> 7;
    const int gcol = n0 + bn, zsh = (bn & 7) * 4;

    float acc[4][4][4];
#pragma unroll
    for (int i = 0; i < 4; i++)
#pragma unroll
        for (int j = 0; j < 4; j++)
#pragma unroll
            for (int k = 0; k < 4; k++) acc[i][j][k] = 0.f;

    float4 xa0, xa1; u32 dq, dz; float ds;

#define LDR_DN(kt) do {                                                          \
    xa0 = *(const float4*)(hp0 + (kt) * 16);                                     \
    xa1 = *(const float4*)(hp1 + (kt) * 16);                                     \
    size_t wr = (size_t)((kt) * 2 + kh) * N2 + gcol;                             \
    dq = __ldg((const u32*)dqw + wr);                                            \
    int g = (kt) >> 3;                                                           \
    ds = __ldg(dsc + (size_t)g * N2 + gcol);                                     \
    dz = __ldg((const u32*)dqz + (size_t)g * (N2/8) + (gcol >> 3));              \
} while (0)

#define STR_DN(st) do {                                                          \
    float* a = AsS + (st) * 128 * PADK;                                          \
    *(float4*)(a + arow0 * PADK + acq * 4) = cvt4(xa0);                          \
    *(float4*)(a + arow1 * PADK + acq * 4) = cvt4(xa1);                          \
    float* bb = BsS + (st) * 128 * PADK + bn * PADK + kh * 8;                    \
    float s = ds, nzt = -((float)(((dz >> zsh) & 15) + 1)) * s;                  \
    deq8(dq, s, nzt, bb);                                                        \
} while (0)

    LDR_DN(0);
    STR_DN(0);
    __syncthreads();

    const int NK = N1 / 16;   // 688
    for (int kt = 0; kt < NK; ++kt){
        const int cur = kt & 1;
        if (kt + 1 < NK) LDR_DN(kt + 1);

        const float* Ab = AsS + cur * 128 * PADK + (warpM * 64 + r) * PADK + c;
        const float* Bb = BsS + cur * 128 * PADK + (warpN * 32 + r) * PADK + c;
#pragma unroll
        for (int k8 = 0; k8 < 16; k8 += 8){
            u32 af[4][4];
#pragma unroll
            for (int mt = 0; mt < 4; mt++){
                const float* p = Ab + mt * 16 * PADK + k8;
                af[mt][0] = __float_as_uint(p[0]);
                af[mt][1] = __float_as_uint(p[8 * PADK]);
                af[mt][2] = __float_as_uint(p[4]);
                af[mt][3] = __float_as_uint(p[8 * PADK + 4]);
            }
            u32 bf[4][2];
#pragma unroll
            for (int nt = 0; nt < 4; nt++){
                const float* p = Bb + nt * 8 * PADK + k8;
                bf[nt][0] = __float_as_uint(p[0]); bf[nt][1] = __float_as_uint(p[4]);
            }
#pragma unroll
            for (int mt = 0; mt < 4; mt++)
#pragma unroll
                for (int nt = 0; nt < 4; nt++)
                    mma8(acc[mt][nt], af[mt], bf[nt]);
        }

        if (kt + 1 < NK) STR_DN((kt + 1) & 1);
        __syncthreads();
    }
#undef LDR_DN
#undef STR_DN

#pragma unroll
    for (int mt = 0; mt < 4; mt++)
#pragma unroll
        for (int nt = 0; nt < 4; nt++){
            const int row = m0 + warpM * 64 + mt * 16 + r;
            const int col = n0 + warpN * 32 + nt * 8 + c * 2;
            float* op = out + (size_t)row * N2 + col;
            const float* a = acc[mt][nt];
            *(float2*)op            = make_float2(a[0], a[1]);
            *(float2*)(op + 8 * N2) = make_float2(a[2], a[3]);
        }
}

// ---------------------------------------------------------------------------
// Host launcher
// ---------------------------------------------------------------------------
extern "C" void kernel_launch(void* const* d_in, const int* in_sizes, int n_in,
                              void* d_out, int out_size)
{
    (void)in_sizes; (void)n_in; (void)out_size;
    const float* x   = (const float*)d_in[0];
    const int*   gqw = (const int*)  d_in[1];
    const float* gsc = (const float*)d_in[2];
    const int*   gqz = (const int*)  d_in[3];
    const int*   uqw = (const int*)  d_in[4];
    const float* usc = (const float*)d_in[5];
    const int*   uqz = (const int*)  d_in[6];
    const int*   dqw = (const int*)  d_in[7];
    const float* dsc = (const float*)d_in[8];
    const int*   dqz = (const int*)  d_in[9];
    float* out = (float*)d_out;

    static int inited = 0;
    if (!inited){
        cudaFuncSetAttribute(gateup_mma, cudaFuncAttributeMaxDynamicSharedMemorySize, GU_SMEM);
        cudaFuncSetAttribute(down_mma,   cudaFuncAttributeMaxDynamicSharedMemorySize, DN_SMEM);
        inited = 1;
    }

    dim3 gridA(N1 / 128, M_TOT / 128);   // 86 x 32
    gateup_mma<<<gridA, 256, GU_SMEM>>>(x, gqw, gsc, gqz, uqw, usc, uqz);

    dim3 gridB(N2 / 128, M_TOT / 128);   // 32 x 32
    down_mma<<<gridB, 256, DN_SMEM>>>(dqw, dsc, dqz, out);
}

// round 11
// speedup vs baseline: 3.7060x; 1.3681x over previous
#include <cuda_runtime.h>
#include <stdint.h>

typedef unsigned int u32;

#define M_TOT 4096
#define K1    4096
#define N1    11008
#define N2    4096
#define SROW  36                    // floats per smem row: 32 + 4 pad (stride 144B = 4-bank step)
#define STAGE_A (128 * SROW)        // floats per stage per array (18432 B)

// scratch: tf32-rounded x; h = silu(g)*u stored tf32-rounded
__device__ float g_xr[(size_t)M_TOT * K1];
__device__ float g_h [(size_t)M_TOT * N1];

// ---------------------------------------------------------------------------
// helpers
// ---------------------------------------------------------------------------
static __device__ __forceinline__ u32 s2u(const void* p){
    u32 a; asm("{ .reg .u64 t; cvta.to.shared.u64 t, %1; cvt.u32.u64 %0, t; }":"=r"(a):"l"(p)); return a;
}
static __device__ __forceinline__ u32 tf32u(float x){
    u32 r; asm("cvt.rna.tf32.f32 %0, %1;" : "=r"(r) : "f"(x)); return r;
}
static __device__ __forceinline__ float silu_f(float g){ return g / (1.f + __expf(-g)); }

static __device__ __forceinline__ void mma8(float* d, const u32* a, const u32* b){
    asm volatile("mma.sync.aligned.m16n8k8.row.col.f32.tf32.tf32.f32 "
        "{%0,%1,%2,%3}, {%4,%5,%6,%7}, {%8,%9}, {%0,%1,%2,%3};"
        : "+f"(d[0]), "+f"(d[1]), "+f"(d[2]), "+f"(d[3])
        : "r"(a[0]), "r"(a[1]), "r"(a[2]), "r"(a[3]), "r"(b[0]), "r"(b[1]));
}
static __device__ __forceinline__ void ldsm4(u32 addr, u32* r){
    asm volatile("ldmatrix.sync.aligned.m8n8.x4.shared.b16 {%0,%1,%2,%3}, [%4];"
        : "=r"(r[0]), "=r"(r[1]), "=r"(r[2]), "=r"(r[3]) : "r"(addr));
}
static __device__ __forceinline__ void cpa16(u32 dst, const void* src){
    asm volatile("cp.async.ca.shared.global [%0], [%1], 16;" :: "r"(dst), "l"(src));
}
static __device__ __forceinline__ void cpcommit(){ asm volatile("cp.async.commit_group;" ::: "memory"); }
static __device__ __forceinline__ void cpwait0(){ asm volatile("cp.async.wait_group 0;" ::: "memory"); }

// dequant one packed int32 (8 int4 ascending k) -> 8 tf32 floats
static __device__ __forceinline__ void deq8(u32 q, float s, float nzt, float* dst){
    float4 a, b;
    a.x = __uint_as_float(tf32u(fmaf((float)( q        & 15), s, nzt)));
    a.y = __uint_as_float(tf32u(fmaf((float)((q >>  4) & 15), s, nzt)));
    a.z = __uint_as_float(tf32u(fmaf((float)((q >>  8) & 15), s, nzt)));
    a.w = __uint_as_float(tf32u(fmaf((float)((q >> 12) & 15), s, nzt)));
    b.x = __uint_as_float(tf32u(fmaf((float)((q >> 16) & 15), s, nzt)));
    b.y = __uint_as_float(tf32u(fmaf((float)((q >> 20) & 15), s, nzt)));
    b.z = __uint_as_float(tf32u(fmaf((float)((q >> 24) & 15), s, nzt)));
    b.w = __uint_as_float(tf32u(fmaf((float)((q >> 28) & 15), s, nzt)));
    *(float4*)dst = a; *(float4*)(dst + 4) = b;
}

// ---------------------------------------------------------------------------
// Kernel 0: pre-round x to tf32
// ---------------------------------------------------------------------------
__global__ void roundx_k(const float* __restrict__ x){
    size_t i = (size_t)blockIdx.x * blockDim.x + threadIdx.x;
    float4 v = ((const float4*)x)[i];
    v.x = __uint_as_float(tf32u(v.x)); v.y = __uint_as_float(tf32u(v.y));
    v.z = __uint_as_float(tf32u(v.z)); v.w = __uint_as_float(tf32u(v.w));
    ((float4*)g_xr)[i] = v;
}

// ---------------------------------------------------------------------------
// Kernel A: fused gate+up GEMM (M=4096,K=4096,N=11008) + silu*mul -> g_h
// CTA 128x128, BK=32, 2-stage, 8 warps = 2(M) x 4(N), warp tile 64x32 dual.
// A via cp.async (pre-rounded, 4 chunks/thread), W via LDG+dequant+STS,
// fragments via ldmatrix.x4.
// ---------------------------------------------------------------------------
#define GU_SMEM (3 * 2 * STAGE_A * 4)   // 110592 B

__global__ __launch_bounds__(256, 1)
void gateup_mma(const int* __restrict__ gqw, const float* __restrict__ gsc, const int* __restrict__ gqz,
                const int* __restrict__ uqw, const float* __restrict__ usc, const int* __restrict__ uqz)
{
    extern __shared__ float sm[];
    float* A0 = sm;
    float* G0 = sm + 2 * STAGE_A;
    float* U0 = sm + 4 * STAGE_A;
    const u32 sbA = s2u(A0), sbG = s2u(G0), sbU = s2u(U0);

    const int tid = threadIdx.x, wid = tid >> 5, lid = tid & 31;
    const int warpM = wid >> 2, warpN = wid & 3;
    const int n0 = blockIdx.x * 128, m0 = blockIdx.y * 128;
    const int r = lid >> 2, c = lid & 3;

    // cp.async A: 4 x 16B per thread (128 rows x 32 k floats = 1024 chunks)
    u32 adst[4]; const float* asrc[4];
#pragma unroll
    for (int i = 0; i < 4; i++){
        int id = tid + i * 256, row = id >> 3, kb = id & 7;
        adst[i] = sbA + (u32)((row * SROW + kb * 4) * 4);
        asrc[i] = g_xr + (size_t)(m0 + row) * K1 + kb * 4;
    }
    // weight loader: col = tid&127, two packed k-words (kr, kr+1), kr in {0,2}
    const int bn = tid & 127, kr = (tid >> 7) * 2;
    const int gcol = n0 + bn, zsh = (bn & 7) * 4;

    // ldmatrix lane addresses (stage 0)
    const int g8 = lid >> 3, lr = lid & 7;
    u32 almA[4];
#pragma unroll
    for (int mt = 0; mt < 4; mt++){
        int row = warpM * 64 + mt * 16 + (g8 & 1) * 8 + lr;
        almA[mt] = sbA + (u32)(row * SROW * 4) + (u32)((g8 >> 1) * 16);
    }
    const int brow = ((lid >> 4) & 1) * 8 + lr;
    const int bcol = ((lid >> 3) & 1) * 16;
    u32 almG[2], almU[2];
#pragma unroll
    for (int p = 0; p < 2; p++){
        int row = warpN * 32 + p * 16 + brow;
        almG[p] = sbG + (u32)(row * SROW * 4) + (u32)bcol;
        almU[p] = sbU + (u32)(row * SROW * 4) + (u32)bcol;
    }

    float accG[4][4][4], accU[4][4][4];
#pragma unroll
    for (int i = 0; i < 4; i++)
#pragma unroll
        for (int j = 0; j < 4; j++)
#pragma unroll
            for (int k = 0; k < 4; k++){ accG[i][j][k] = 0.f; accU[i][j][k] = 0.f; }

    const int NK = K1 / 32;   // 128
    u32 gq0, gq1, uq0, uq1, gz, uz; float gs, us;

    // ---- prologue: stage 0 ----
#pragma unroll
    for (int i = 0; i < 4; i++) cpa16(adst[i], asrc[i]);
    cpcommit();
    {
        size_t wr = (size_t)kr * N1 + gcol;
        gq0 = __ldg((const u32*)gqw + wr); gq1 = __ldg((const u32*)gqw + wr + N1);
        uq0 = __ldg((const u32*)uqw + wr); uq1 = __ldg((const u32*)uqw + wr + N1);
        gs = __ldg(gsc + gcol);  us = __ldg(usc + gcol);
        gz = __ldg((const u32*)gqz + (gcol >> 3)); uz = __ldg((const u32*)uqz + (gcol >> 3));
    }
    {
        float* gdst = G0 + bn * SROW + kr * 8;
        float nzt = -((float)(((gz >> zsh) & 15) + 1)) * gs;
        deq8(gq0, gs, nzt, gdst); deq8(gq1, gs, nzt, gdst + 8);
        float* udst = U0 + bn * SROW + kr * 8;
        nzt = -((float)(((uz >> zsh) & 15) + 1)) * us;
        deq8(uq0, us, nzt, udst); deq8(uq1, us, nzt, udst + 8);
    }
    cpwait0();
    __syncthreads();

    for (int kt = 0; kt < NK; ++kt){
        const int cur = kt & 1, nxt = cur ^ 1;
        if (kt + 1 < NK){
#pragma unroll
            for (int i = 0; i < 4; i++)
                cpa16(adst[i] + (u32)(nxt * STAGE_A * 4), asrc[i] + (size_t)(kt + 1) * 32);
            cpcommit();
            size_t wr = (size_t)((kt + 1) * 4 + kr) * N1 + gcol;
            gq0 = __ldg((const u32*)gqw + wr); gq1 = __ldg((const u32*)gqw + wr + N1);
            uq0 = __ldg((const u32*)uqw + wr); uq1 = __ldg((const u32*)uqw + wr + N1);
            int grp = (kt + 1) >> 2;
            gs = __ldg(gsc + (size_t)grp * N1 + gcol);
            us = __ldg(usc + (size_t)grp * N1 + gcol);
            gz = __ldg((const u32*)gqz + (size_t)grp * (N1 / 8) + (gcol >> 3));
            uz = __ldg((const u32*)uqz + (size_t)grp * (N1 / 8) + (gcol >> 3));
        }

        const u32 so = (u32)(cur * STAGE_A * 4);
#pragma unroll
        for (int j = 0; j < 4; j++){
            u32 af[4][4], bg[2][4], bu[2][4];
#pragma unroll
            for (int mt = 0; mt < 4; mt++) ldsm4(almA[mt] + so + j * 32, af[mt]);
#pragma unroll
            for (int p = 0; p < 2; p++){ ldsm4(almG[p] + so + j * 32, bg[p]); ldsm4(almU[p] + so + j * 32, bu[p]); }
#pragma unroll
            for (int mt = 0; mt < 4; mt++)
#pragma unroll
                for (int nt = 0; nt < 4; nt++){
                    mma8(accG[mt][nt], af[mt], &bg[nt >> 1][(nt & 1) * 2]);
                    mma8(accU[mt][nt], af[mt], &bu[nt >> 1][(nt & 1) * 2]);
                }
        }

        if (kt + 1 < NK){
            float* gdst = G0 + nxt * STAGE_A + bn * SROW + kr * 8;
            float nzt = -((float)(((gz >> zsh) & 15) + 1)) * gs;
            deq8(gq0, gs, nzt, gdst); deq8(gq1, gs, nzt, gdst + 8);
            float* udst = U0 + nxt * STAGE_A + bn * SROW + kr * 8;
            nzt = -((float)(((uz >> zsh) & 15) + 1)) * us;
            deq8(uq0, us, nzt, udst); deq8(uq1, us, nzt, udst + 8);
            cpwait0();
        }
        __syncthreads();
    }

    // epilogue: h = silu(g) * u, tf32-rounded
#pragma unroll
    for (int mt = 0; mt < 4; mt++)
#pragma unroll
        for (int nt = 0; nt < 4; nt++){
            const int row = m0 + warpM * 64 + mt * 16 + r;
            const int col = n0 + warpN * 32 + nt * 8 + c * 2;
            float* hp = g_h + (size_t)row * N1 + col;
            const float* a = accG[mt][nt]; const float* b = accU[mt][nt];
            float2 v0, v1;
            v0.x = __uint_as_float(tf32u(silu_f(a[0]) * b[0]));
            v0.y = __uint_as_float(tf32u(silu_f(a[1]) * b[1]));
            v1.x = __uint_as_float(tf32u(silu_f(a[2]) * b[2]));
            v1.y = __uint_as_float(tf32u(silu_f(a[3]) * b[3]));
            *(float2*)hp            = v0;
            *(float2*)(hp + 8 * N1) = v1;
        }
}

// ---------------------------------------------------------------------------
// Kernel B: down GEMM out = h @ Wd (M=4096, K=11008, N=4096)
// ---------------------------------------------------------------------------
#define DN_SMEM (2 * 2 * STAGE_A * 4)   // 73728 B

__global__ __launch_bounds__(256, 1)
void down_mma(const int* __restrict__ dqw, const float* __restrict__ dsc,
              const int* __restrict__ dqz, float* __restrict__ out)
{
    extern __shared__ float sm[];
    float* A0 = sm;
    float* B0 = sm + 2 * STAGE_A;
    const u32 sbA = s2u(A0), sbB = s2u(B0);

    const int tid = threadIdx.x, wid = tid >> 5, lid = tid & 31;
    const int warpM = wid >> 2, warpN = wid & 3;
    const int n0 = blockIdx.x * 128, m0 = blockIdx.y * 128;
    const int r = lid >> 2, c = lid & 3;

    u32 adst[4]; const float* asrc[4];
#pragma unroll
    for (int i = 0; i < 4; i++){
        int id = tid + i * 256, row = id >> 3, kb = id & 7;
        adst[i] = sbA + (u32)((row * SROW + kb * 4) * 4);
        asrc[i] = g_h + (size_t)(m0 + row) * N1 + kb * 4;
    }
    const int bn = tid & 127, kr = (tid >> 7) * 2;
    const int gcol = n0 + bn, zsh = (bn & 7) * 4;

    const int g8 = lid >> 3, lr = lid & 7;
    u32 almA[4];
#pragma unroll
    for (int mt = 0; mt < 4; mt++){
        int row = warpM * 64 + mt * 16 + (g8 & 1) * 8 + lr;
        almA[mt] = sbA + (u32)(row * SROW * 4) + (u32)((g8 >> 1) * 16);
    }
    const int brow = ((lid >> 4) & 1) * 8 + lr;
    const int bcol = ((lid >> 3) & 1) * 16;
    u32 almB[2];
#pragma unroll
    for (int p = 0; p < 2; p++){
        int row = warpN * 32 + p * 16 + brow;
        almB[p] = sbB + (u32)(row * SROW * 4) + (u32)bcol;
    }

    float acc[4][4][4];
#pragma unroll
    for (int i = 0; i < 4; i++)
#pragma unroll
        for (int j = 0; j < 4; j++)
#pragma unroll
            for (int k = 0; k < 4; k++) acc[i][j][k] = 0.f;

    const int NK = N1 / 32;   // 344
    u32 dq0, dq1, dz; float ds;

#pragma unroll
    for (int i = 0; i < 4; i++) cpa16(adst[i], asrc[i]);
    cpcommit();
    {
        size_t wr = (size_t)kr * N2 + gcol;
        dq0 = __ldg((const u32*)dqw + wr); dq1 = __ldg((const u32*)dqw + wr + N2);
        ds = __ldg(dsc + gcol);
        dz = __ldg((const u32*)dqz + (gcol >> 3));
    }
    {
        float* bdst = B0 + bn * SROW + kr * 8;
        float nzt = -((float)(((dz >> zsh) & 15) + 1)) * ds;
        deq8(dq0, ds, nzt, bdst); deq8(dq1, ds, nzt, bdst + 8);
    }
    cpwait0();
    __syncthreads();

    for (int kt = 0; kt < NK; ++kt){
        const int cur = kt & 1, nxt = cur ^ 1;
        if (kt + 1 < NK){
#pragma unroll
            for (int i = 0; i < 4; i++)
                cpa16(adst[i] + (u32)(nxt * STAGE_A * 4), asrc[i] + (size_t)(kt + 1) * 32);
            cpcommit();
            size_t wr = (size_t)((kt + 1) * 4 + kr) * N2 + gcol;
            dq0 = __ldg((const u32*)dqw + wr); dq1 = __ldg((const u32*)dqw + wr + N2);
            int grp = (kt + 1) >> 2;
            ds = __ldg(dsc + (size_t)grp * N2 + gcol);
            dz = __ldg((const u32*)dqz + (size_t)grp * (N2 / 8) + (gcol >> 3));
        }

        const u32 so = (u32)(cur * STAGE_A * 4);
#pragma unroll
        for (int j = 0; j < 4; j++){
            u32 af[4][4], bf[2][4];
#pragma unroll
            for (int mt = 0; mt < 4; mt++) ldsm4(almA[mt] + so + j * 32, af[mt]);
#pragma unroll
            for (int p = 0; p < 2; p++) ldsm4(almB[p] + so + j * 32, bf[p]);
#pragma unroll
            for (int mt = 0; mt < 4; mt++)
#pragma unroll
                for (int nt = 0; nt < 4; nt++)
                    mma8(acc[mt][nt], af[mt], &bf[nt >> 1][(nt & 1) * 2]);
        }

        if (kt + 1 < NK){
            float* bdst = B0 + nxt * STAGE_A + bn * SROW + kr * 8;
            float nzt = -((float)(((dz >> zsh) & 15) + 1)) * ds;
            deq8(dq0, ds, nzt, bdst); deq8(dq1, ds, nzt, bdst + 8);
            cpwait0();
        }
        __syncthreads();
    }

#pragma unroll
    for (int mt = 0; mt < 4; mt++)
#pragma unroll
        for (int nt = 0; nt < 4; nt++){
            const int row = m0 + warpM * 64 + mt * 16 + r;
            const int col = n0 + warpN * 32 + nt * 8 + c * 2;
            float* op = out + (size_t)row * N2 + col;
            const float* a = acc[mt][nt];
            *(float2*)op            = make_float2(a[0], a[1]);
            *(float2*)(op + 8 * N2) = make_float2(a[2], a[3]);
        }
}

// ---------------------------------------------------------------------------
// Host launcher
// ---------------------------------------------------------------------------
extern "C" void kernel_launch(void* const* d_in, const int* in_sizes, int n_in,
                              void* d_out, int out_size)
{
    (void)in_sizes; (void)n_in; (void)out_size;
    const float* x   = (const float*)d_in[0];
    const int*   gqw = (const int*)  d_in[1];
    const float* gsc = (const float*)d_in[2];
    const int*   gqz = (const int*)  d_in[3];
    const int*   uqw = (const int*)  d_in[4];
    const float* usc = (const float*)d_in[5];
    const int*   uqz = (const int*)  d_in[6];
    const int*   dqw = (const int*)  d_in[7];
    const float* dsc = (const float*)d_in[8];
    const int*   dqz = (const int*)  d_in[9];
    float* out = (float*)d_out;

    cudaFuncSetAttribute(gateup_mma, cudaFuncAttributeMaxDynamicSharedMemorySize, GU_SMEM);
    cudaFuncSetAttribute(down_mma,   cudaFuncAttributeMaxDynamicSharedMemorySize, DN_SMEM);

    roundx_k<<<(int)((size_t)M_TOT * K1 / 4 / 256), 256>>>(x);

    dim3 gridA(N1 / 128, M_TOT / 128);   // 86 x 32
    gateup_mma<<<gridA, 256, GU_SMEM>>>(gqw, gsc, gqz, uqw, usc, uqz);

    dim3 gridB(N2 / 128, M_TOT / 128);   // 32 x 32
    down_mma<<<gridB, 256, DN_SMEM>>>(dqw, dsc, dqz, out);
}

// round 12
// speedup vs baseline: 3.7268x; 1.0056x over previous
#include <cuda_runtime.h>
#include <stdint.h>

typedef unsigned int u32;

#define M_TOT 4096
#define K1    4096
#define N1    11008
#define N2    4096
#define SROW  68                    // floats per smem row: 64 + 4 pad (stride 272B, conflict-free)
#define STAGE (128 * SROW)          // floats per stage per array (34816 B)

// scratch: tf32-rounded x; h = silu(g)*u stored tf32-rounded
__device__ float g_xr[(size_t)M_TOT * K1];
__device__ float g_h [(size_t)M_TOT * N1];

// ---------------------------------------------------------------------------
// helpers
// ---------------------------------------------------------------------------
static __device__ __forceinline__ u32 s2u(const void* p){
    u32 a; asm("{ .reg .u64 t; cvta.to.shared.u64 t, %1; cvt.u32.u64 %0, t; }":"=r"(a):"l"(p)); return a;
}
static __device__ __forceinline__ u32 tf32u(float x){
    u32 r; asm("cvt.rna.tf32.f32 %0, %1;" : "=r"(r) : "f"(x)); return r;
}
static __device__ __forceinline__ float silu_f(float g){ return g / (1.f + __expf(-g)); }

static __device__ __forceinline__ void mma8(float* d, const u32* a, const u32* b){
    asm volatile("mma.sync.aligned.m16n8k8.row.col.f32.tf32.tf32.f32 "
        "{%0,%1,%2,%3}, {%4,%5,%6,%7}, {%8,%9}, {%0,%1,%2,%3};"
        : "+f"(d[0]), "+f"(d[1]), "+f"(d[2]), "+f"(d[3])
        : "r"(a[0]), "r"(a[1]), "r"(a[2]), "r"(a[3]), "r"(b[0]), "r"(b[1]));
}
static __device__ __forceinline__ void ldsm4(u32 addr, u32* r){
    asm volatile("ldmatrix.sync.aligned.m8n8.x4.shared.b16 {%0,%1,%2,%3}, [%4];"
        : "=r"(r[0]), "=r"(r[1]), "=r"(r[2]), "=r"(r[3]) : "r"(addr));
}
static __device__ __forceinline__ void cpa16(u32 dst, const void* src){
    asm volatile("cp.async.cg.shared.global [%0], [%1], 16;" :: "r"(dst), "l"(src));
}
static __device__ __forceinline__ void cpcommit(){ asm volatile("cp.async.commit_group;" ::: "memory"); }
static __device__ __forceinline__ void cpwait0(){ asm volatile("cp.async.wait_group 0;" ::: "memory"); }

// dequant one packed int32 (8 int4 ascending k) -> 8 tf32 floats
static __device__ __forceinline__ void deq8(u32 q, float s, float nzt, float* dst){
    float4 a, b;
    a.x = __uint_as_float(tf32u(fmaf((float)( q        & 15), s, nzt)));
    a.y = __uint_as_float(tf32u(fmaf((float)((q >>  4) & 15), s, nzt)));
    a.z = __uint_as_float(tf32u(fmaf((float)((q >>  8) & 15), s, nzt)));
    a.w = __uint_as_float(tf32u(fmaf((float)((q >> 12) & 15), s, nzt)));
    b.x = __uint_as_float(tf32u(fmaf((float)((q >> 16) & 15), s, nzt)));
    b.y = __uint_as_float(tf32u(fmaf((float)((q >> 20) & 15), s, nzt)));
    b.z = __uint_as_float(tf32u(fmaf((float)((q >> 24) & 15), s, nzt)));
    b.w = __uint_as_float(tf32u(fmaf((float)((q >> 28) & 15), s, nzt)));
    *(float4*)dst = a; *(float4*)(dst + 4) = b;
}

// ---------------------------------------------------------------------------
// Kernel 0: pre-round x to tf32
// ---------------------------------------------------------------------------
__global__ void roundx_k(const float* __restrict__ x){
    size_t i = (size_t)blockIdx.x * blockDim.x + threadIdx.x;
    float4 v = ((const float4*)x)[i];
    v.x = __uint_as_float(tf32u(v.x)); v.y = __uint_as_float(tf32u(v.y));
    v.z = __uint_as_float(tf32u(v.z)); v.w = __uint_as_float(tf32u(v.w));
    ((float4*)g_xr)[i] = v;
}

// ---------------------------------------------------------------------------
// Kernel A: fused gate+up GEMM (M=4096,K=4096,N=11008) + silu*mul -> g_h
// CTA 128x128, BK=64, 2-stage, 8 warps = 2(M) x 4(N), warp tile 64x32 dual.
// ---------------------------------------------------------------------------
#define GU_SMEM (3 * 2 * STAGE * 4)   // 208896 B

__global__ __launch_bounds__(256, 1)
void gateup_mma(const int* __restrict__ gqw, const float* __restrict__ gsc, const int* __restrict__ gqz,
                const int* __restrict__ uqw, const float* __restrict__ usc, const int* __restrict__ uqz)
{
    extern __shared__ float sm[];
    float* A0 = sm;
    float* G0 = sm + 2 * STAGE;
    float* U0 = sm + 4 * STAGE;
    const u32 sbA = s2u(A0), sbG = s2u(G0), sbU = s2u(U0);

    const int tid = threadIdx.x, wid = tid >> 5, lid = tid & 31;
    const int warpM = wid >> 2, warpN = wid & 3;
    const int n0 = blockIdx.x * 128, m0 = blockIdx.y * 128;
    const int r = lid >> 2, c = lid & 3;

    const float* xbase = g_xr + (size_t)m0 * K1;
    // weight loader: col = tid&127, four packed k-words starting at kr
    const int bn = tid & 127, kr = (tid >> 7) * 4;
    const int gcol = n0 + bn, zsh = (bn & 7) * 4;

    // ldmatrix lane addresses (stage 0)
    const int g8 = lid >> 3, lr = lid & 7;
    u32 almA[4];
#pragma unroll
    for (int mt = 0; mt < 4; mt++){
        int row = warpM * 64 + mt * 16 + (g8 & 1) * 8 + lr;
        almA[mt] = sbA + (u32)(row * SROW * 4) + (u32)((g8 >> 1) * 16);
    }
    const int brow = ((lid >> 4) & 1) * 8 + lr;
    const int bcol = ((lid >> 3) & 1) * 16;
    u32 almG[2], almU[2];
#pragma unroll
    for (int p = 0; p < 2; p++){
        int row = warpN * 32 + p * 16 + brow;
        almG[p] = sbG + (u32)(row * SROW * 4) + (u32)bcol;
        almU[p] = sbU + (u32)(row * SROW * 4) + (u32)bcol;
    }

    float accG[4][4][4], accU[4][4][4];
#pragma unroll
    for (int i = 0; i < 4; i++)
#pragma unroll
        for (int j = 0; j < 4; j++)
#pragma unroll
            for (int k = 0; k < 4; k++){ accG[i][j][k] = 0.f; accU[i][j][k] = 0.f; }

    const int NK = K1 / 64;   // 64
    u32 gq[4], uq[4], gz, uz; float gs, us;

#define ACOPY_GU(st, kt1) do {                                                   \
    u32 so_ = sbA + (u32)((st) * STAGE * 4);                                     \
    _Pragma("unroll")                                                            \
    for (int i_ = 0; i_ < 8; i_++){                                              \
        int id_ = tid + i_ * 256, row_ = id_ >> 4, kb_ = id_ & 15;               \
        cpa16(so_ + (u32)((row_ * SROW + kb_ * 4) * 4),                          \
              xbase + (size_t)row_ * K1 + (size_t)(kt1) * 64 + kb_ * 4);         \
    }                                                                            \
    cpcommit();                                                                  \
} while (0)

#define WLOAD_GU(kt1) do {                                                       \
    size_t wr_ = (size_t)((kt1) * 8 + kr) * N1 + gcol;                           \
    _Pragma("unroll")                                                            \
    for (int w_ = 0; w_ < 4; w_++){                                              \
        gq[w_] = __ldg((const u32*)gqw + wr_ + (size_t)w_ * N1);                 \
        uq[w_] = __ldg((const u32*)uqw + wr_ + (size_t)w_ * N1);                 \
    }                                                                            \
    int grp_ = (kt1) >> 1;                                                       \
    gs = __ldg(gsc + (size_t)grp_ * N1 + gcol);                                  \
    us = __ldg(usc + (size_t)grp_ * N1 + gcol);                                  \
    gz = __ldg((const u32*)gqz + (size_t)grp_ * (N1 / 8) + (gcol >> 3));         \
    uz = __ldg((const u32*)uqz + (size_t)grp_ * (N1 / 8) + (gcol >> 3));         \
} while (0)

#define WSTORE_GU(st) do {                                                       \
    float* gd_ = G0 + (st) * STAGE + bn * SROW + kr * 8;                         \
    float nz_ = -((float)(((gz >> zsh) & 15) + 1)) * gs;                         \
    _Pragma("unroll")                                                            \
    for (int w_ = 0; w_ < 4; w_++) deq8(gq[w_], gs, nz_, gd_ + w_ * 8);          \
    float* ud_ = U0 + (st) * STAGE + bn * SROW + kr * 8;                         \
    nz_ = -((float)(((uz >> zsh) & 15) + 1)) * us;                               \
    _Pragma("unroll")                                                            \
    for (int w_ = 0; w_ < 4; w_++) deq8(uq[w_], us, nz_, ud_ + w_ * 8);          \
} while (0)

    // prologue: stage 0
    ACOPY_GU(0, 0);
    WLOAD_GU(0);
    WSTORE_GU(0);
    cpwait0();
    __syncthreads();

    for (int kt = 0; kt < NK; ++kt){
        const int cur = kt & 1, nxt = cur ^ 1;
        if (kt + 1 < NK){
            ACOPY_GU(nxt, kt + 1);
            WLOAD_GU(kt + 1);
        }

        const u32 so = (u32)(cur * STAGE * 4);
#pragma unroll
        for (int j = 0; j < 8; j++){
            u32 af[4][4], bg[2][4], bu[2][4];
#pragma unroll
            for (int mt = 0; mt < 4; mt++) ldsm4(almA[mt] + so + j * 32, af[mt]);
#pragma unroll
            for (int p = 0; p < 2; p++){ ldsm4(almG[p] + so + j * 32, bg[p]); ldsm4(almU[p] + so + j * 32, bu[p]); }
#pragma unroll
            for (int mt = 0; mt < 4; mt++)
#pragma unroll
                for (int nt = 0; nt < 4; nt++){
                    mma8(accG[mt][nt], af[mt], &bg[nt >> 1][(nt & 1) * 2]);
                    mma8(accU[mt][nt], af[mt], &bu[nt >> 1][(nt & 1) * 2]);
                }
        }

        if (kt + 1 < NK){
            WSTORE_GU(nxt);
            cpwait0();
        }
        __syncthreads();
    }
#undef ACOPY_GU
#undef WLOAD_GU
#undef WSTORE_GU

    // epilogue: h = silu(g) * u, tf32-rounded
#pragma unroll
    for (int mt = 0; mt < 4; mt++)
#pragma unroll
        for (int nt = 0; nt < 4; nt++){
            const int row = m0 + warpM * 64 + mt * 16 + r;
            const int col = n0 + warpN * 32 + nt * 8 + c * 2;
            float* hp = g_h + (size_t)row * N1 + col;
            const float* a = accG[mt][nt]; const float* b = accU[mt][nt];
            float2 v0, v1;
            v0.x = __uint_as_float(tf32u(silu_f(a[0]) * b[0]));
            v0.y = __uint_as_float(tf32u(silu_f(a[1]) * b[1]));
            v1.x = __uint_as_float(tf32u(silu_f(a[2]) * b[2]));
            v1.y = __uint_as_float(tf32u(silu_f(a[3]) * b[3]));
            *(float2*)hp            = v0;
            *(float2*)(hp + 8 * N1) = v1;
        }
}

// ---------------------------------------------------------------------------
// Kernel B: down GEMM out = h @ Wd (M=4096, K=11008, N=4096), BK=64
// ---------------------------------------------------------------------------
#define DN_SMEM (2 * 2 * STAGE * 4)   // 139264 B

__global__ __launch_bounds__(256, 1)
void down_mma(const int* __restrict__ dqw, const float* __restrict__ dsc,
              const int* __restrict__ dqz, float* __restrict__ out)
{
    extern __shared__ float sm[];
    float* A0 = sm;
    float* B0 = sm + 2 * STAGE;
    const u32 sbA = s2u(A0), sbB = s2u(B0);

    const int tid = threadIdx.x, wid = tid >> 5, lid = tid & 31;
    const int warpM = wid >> 2, warpN = wid & 3;
    const int n0 = blockIdx.x * 128, m0 = blockIdx.y * 128;
    const int r = lid >> 2, c = lid & 3;

    const float* xbase = g_h + (size_t)m0 * N1;
    const int bn = tid & 127, kr = (tid >> 7) * 4;
    const int gcol = n0 + bn, zsh = (bn & 7) * 4;

    const int g8 = lid >> 3, lr = lid & 7;
    u32 almA[4];
#pragma unroll
    for (int mt = 0; mt < 4; mt++){
        int row = warpM * 64 + mt * 16 + (g8 & 1) * 8 + lr;
        almA[mt] = sbA + (u32)(row * SROW * 4) + (u32)((g8 >> 1) * 16);
    }
    const int brow = ((lid >> 4) & 1) * 8 + lr;
    const int bcol = ((lid >> 3) & 1) * 16;
    u32 almB[2];
#pragma unroll
    for (int p = 0; p < 2; p++){
        int row = warpN * 32 + p * 16 + brow;
        almB[p] = sbB + (u32)(row * SROW * 4) + (u32)bcol;
    }

    float acc[4][4][4];
#pragma unroll
    for (int i = 0; i < 4; i++)
#pragma unroll
        for (int j = 0; j < 4; j++)
#pragma unroll
            for (int k = 0; k < 4; k++) acc[i][j][k] = 0.f;

    const int NK = N1 / 64;   // 172
    u32 dq[4], dz; float ds;

#define ACOPY_DN(st, kt1) do {                                                   \
    u32 so_ = sbA + (u32)((st) * STAGE * 4);                                     \
    _Pragma("unroll")                                                            \
    for (int i_ = 0; i_ < 8; i_++){                                              \
        int id_ = tid + i_ * 256, row_ = id_ >> 4, kb_ = id_ & 15;               \
        cpa16(so_ + (u32)((row_ * SROW + kb_ * 4) * 4),                          \
              xbase + (size_t)row_ * N1 + (size_t)(kt1) * 64 + kb_ * 4);         \
    }                                                                            \
    cpcommit();                                                                  \
} while (0)

#define WLOAD_DN(kt1) do {                                                       \
    size_t wr_ = (size_t)((kt1) * 8 + kr) * N2 + gcol;                           \
    _Pragma("unroll")                                                            \
    for (int w_ = 0; w_ < 4; w_++)                                               \
        dq[w_] = __ldg((const u32*)dqw + wr_ + (size_t)w_ * N2);                 \
    int grp_ = (kt1) >> 1;                                                       \
    ds = __ldg(dsc + (size_t)grp_ * N2 + gcol);                                  \
    dz = __ldg((const u32*)dqz + (size_t)grp_ * (N2 / 8) + (gcol >> 3));         \
} while (0)

#define WSTORE_DN(st) do {                                                       \
    float* bd_ = B0 + (st) * STAGE + bn * SROW + kr * 8;                         \
    float nz_ = -((float)(((dz >> zsh) & 15) + 1)) * ds;                         \
    _Pragma("unroll")                                                            \
    for (int w_ = 0; w_ < 4; w_++) deq8(dq[w_], ds, nz_, bd_ + w_ * 8);          \
} while (0)

    ACOPY_DN(0, 0);
    WLOAD_DN(0);
    WSTORE_DN(0);
    cpwait0();
    __syncthreads();

    for (int kt = 0; kt < NK; ++kt){
        const int cur = kt & 1, nxt = cur ^ 1;
        if (kt + 1 < NK){
            ACOPY_DN(nxt, kt + 1);
            WLOAD_DN(kt + 1);
        }

        const u32 so = (u32)(cur * STAGE * 4);
#pragma unroll
        for (int j = 0; j < 8; j++){
            u32 af[4][4], bf[2][4];
#pragma unroll
            for (int mt = 0; mt < 4; mt++) ldsm4(almA[mt] + so + j * 32, af[mt]);
#pragma unroll
            for (int p = 0; p < 2; p++) ldsm4(almB[p] + so + j * 32, bf[p]);
#pragma unroll
            for (int mt = 0; mt < 4; mt++)
#pragma unroll
                for (int nt = 0; nt < 4; nt++)
                    mma8(acc[mt][nt], af[mt], &bf[nt >> 1][(nt & 1) * 2]);
        }

        if (kt + 1 < NK){
            WSTORE_DN(nxt);
            cpwait0();
        }
        __syncthreads();
    }
#undef ACOPY_DN
#undef WLOAD_DN
#undef WSTORE_DN

#pragma unroll
    for (int mt = 0; mt < 4; mt++)
#pragma unroll
        for (int nt = 0; nt < 4; nt++){
            const int row = m0 + warpM * 64 + mt * 16 + r;
            const int col = n0 + warpN * 32 + nt * 8 + c * 2;
            float* op = out + (size_t)row * N2 + col;
            const float* a = acc[mt][nt];
            *(float2*)op            = make_float2(a[0], a[1]);
            *(float2*)(op + 8 * N2) = make_float2(a[2], a[3]);
        }
}

// ---------------------------------------------------------------------------
// Host launcher
// ---------------------------------------------------------------------------
extern "C" void kernel_launch(void* const* d_in, const int* in_sizes, int n_in,
                              void* d_out, int out_size)
{
    (void)in_sizes; (void)n_in; (void)out_size;
    const float* x   = (const float*)d_in[0];
    const int*   gqw = (const int*)  d_in[1];
    const float* gsc = (const float*)d_in[2];
    const int*   gqz = (const int*)  d_in[3];
    const int*   uqw = (const int*)  d_in[4];
    const float* usc = (const float*)d_in[5];
    const int*   uqz = (const int*)  d_in[6];
    const int*   dqw = (const int*)  d_in[7];
    const float* dsc = (const float*)d_in[8];
    const int*   dqz = (const int*)  d_in[9];
    float* out = (float*)d_out;

    cudaFuncSetAttribute(gateup_mma, cudaFuncAttributeMaxDynamicSharedMemorySize, GU_SMEM);
    cudaFuncSetAttribute(down_mma,   cudaFuncAttributeMaxDynamicSharedMemorySize, DN_SMEM);

    roundx_k<<<(int)((size_t)M_TOT * K1 / 4 / 256), 256>>>(x);

    dim3 gridA(N1 / 128, M_TOT / 128);   // 86 x 32
    gateup_mma<<<gridA, 256, GU_SMEM>>>(gqw, gsc, gqz, uqw, usc, uqz);

    dim3 gridB(N2 / 128, M_TOT / 128);   // 32 x 32
    down_mma<<<gridB, 256, DN_SMEM>>>(dqw, dsc, dqz, out);
}